// round 15
// baseline (speedup 1.0000x reference)
#include <cuda_runtime.h>
#include <cuda_bf16.h>
#include <cuda_fp16.h>
#include <cstddef>
#include <cstdint>

#define Bn   8
#define Nn   8192
#define En   128
#define Hn   8
#define Dn   16
#define WINn 64
#define Wn   129
#define Mrows (Bn*Nn)       // 65536

// Scratch (device globals; allocation-free per harness rules)
__device__ __nv_bfloat16 g_Qh[Mrows * En];
__device__ __nv_bfloat16 g_Ql[Mrows * En];
__device__ __nv_bfloat16 g_Kh[Mrows * En];
__device__ __nv_bfloat16 g_Kl[Mrows * En];
__device__ __nv_bfloat16 g_Vh[Mrows * En];
__device__ __nv_bfloat16 g_Vl[Mrows * En];
__device__ float g_AO[Mrows * En];
__device__ float g_scr[Mrows * En];

// ========================= helpers ============================
__device__ __forceinline__ uint32_t smem_u32(const void* p) {
    uint32_t a;
    asm("{ .reg .u64 t; cvta.to.shared.u64 t, %1; cvt.u32.u64 %0, t; }" : "=r"(a) : "l"(p));
    return a;
}
__device__ __forceinline__ uint32_t cvt_bf16x2(float lo, float hi) {
    uint32_t r;
    asm("cvt.rn.satfinite.bf16x2.f32 %0, %1, %2;" : "=r"(r) : "f"(hi), "f"(lo));
    return r;
}
__device__ __forceinline__ float trunc_hi(float x) {
    return __uint_as_float(__float_as_uint(x) & 0xFFFF0000u);
}
__device__ __forceinline__ uint32_t pack_hi(float f0, float f1) {
    return __byte_perm(__float_as_uint(f0), __float_as_uint(f1), 0x7632);
}
__device__ __forceinline__ uint32_t pack_lo(float f0, float f1) {
    return cvt_bf16x2(f0 - trunc_hi(f0), f1 - trunc_hi(f1));
}
__device__ __forceinline__ void ldm_x4(uint32_t* r, uint32_t addr) {
    asm volatile("ldmatrix.sync.aligned.m8n8.x4.shared.b16 {%0,%1,%2,%3}, [%4];"
        : "=r"(r[0]), "=r"(r[1]), "=r"(r[2]), "=r"(r[3]) : "r"(addr));
}
__device__ __forceinline__ void mma16816(float* c, const uint32_t* a, const uint32_t* b) {
    asm volatile("mma.sync.aligned.m16n8k16.row.col.f32.bf16.bf16.f32 "
        "{%0,%1,%2,%3}, {%4,%5,%6,%7}, {%8,%9}, {%0,%1,%2,%3};"
        : "+f"(c[0]), "+f"(c[1]), "+f"(c[2]), "+f"(c[3])
        : "r"(a[0]), "r"(a[1]), "r"(a[2]), "r"(a[3]), "r"(b[0]), "r"(b[1]));
}

// ===========================================================================
// Projection GEMM body, M=128 tile, 512 threads = 16 warps (4m x 4n);
// 2-way split accumulators (hh+lh chain / hl chain) to break RAW chains.
// ===========================================================================
#define PSTR 136
#define TILE128 (128 * PSTR * 2)          // 34816
#define POFF_BIAS 0
#define POFF_XH 512
#define POFF_XL (512 + TILE128)
#define POFF_WH (512 + 2*TILE128)
#define POFF_WL (512 + 3*TILE128)
#define PROJ_SMEM (512 + 4*TILE128)       // 139776

template <bool SPLIT_OUT>
__device__ __forceinline__ void proj_body(
    const float* __restrict__ X, const float* __restrict__ Wm,
    const float* __restrict__ bias,
    float* __restrict__ C, __nv_bfloat16* __restrict__ Oh, __nv_bfloat16* __restrict__ Ol)
{
    extern __shared__ __align__(16) char psm[];
    float* sbias = (float*)(psm + POFF_BIAS);
    const int t = threadIdx.x;
    const int wid = t >> 5;
    const int lane = t & 31;
    const int row0 = blockIdx.x * 128;

    if (t < 128) sbias[t] = bias[t];

#pragma unroll
    for (int i = 0; i < 8; ++i) {
        int idx = t + i * 512;
        int r  = idx >> 5;
        int kq = (idx & 31) * 4;
        uint32_t so = (uint32_t)(r * PSTR + kq) * 2;
        float4 xv = *(const float4*)&X[(size_t)(row0 + r) * 128 + kq];
        *(uint2*)(psm + POFF_XH + so) = make_uint2(pack_hi(xv.x, xv.y), pack_hi(xv.z, xv.w));
        *(uint2*)(psm + POFF_XL + so) = make_uint2(pack_lo(xv.x, xv.y), pack_lo(xv.z, xv.w));
        float4 wv = *(const float4*)&Wm[(size_t)r * 128 + kq];
        *(uint2*)(psm + POFF_WH + so) = make_uint2(pack_hi(wv.x, wv.y), pack_hi(wv.z, wv.w));
        *(uint2*)(psm + POFF_WL + so) = make_uint2(pack_lo(wv.x, wv.y), pack_lo(wv.z, wv.w));
    }
    __syncthreads();

    const int wm = (wid & 3) * 32;
    const int wn = (wid >> 2) * 32;

    float accP[2][4][4], accQ[2][4][4];
#pragma unroll
    for (int mt = 0; mt < 2; ++mt)
#pragma unroll
        for (int nt = 0; nt < 4; ++nt)
#pragma unroll
            for (int c = 0; c < 4; ++c) { accP[mt][nt][c] = 0.f; accQ[mt][nt][c] = 0.f; }

    const int a_row  = (lane & 7) + ((lane >> 3) & 1) * 8;
    const int a_koff = (lane >> 4) * 8;
    const int b_row  = (lane & 7) + ((lane >> 4) & 1) * 8;
    const int b_koff = ((lane >> 3) & 1) * 8;

    const uint32_t sXh = smem_u32(psm + POFF_XH);
    const uint32_t sXl = smem_u32(psm + POFF_XL);
    const uint32_t sWh = smem_u32(psm + POFF_WH);
    const uint32_t sWl = smem_u32(psm + POFF_WL);

#pragma unroll
    for (int kc8 = 0; kc8 < 8; ++kc8) {
        const int kc = kc8 * 16;
        const uint32_t a0off = (uint32_t)((wm + a_row) * PSTR + kc + a_koff) * 2;
        const uint32_t a1off = (uint32_t)((wm + 16 + a_row) * PSTR + kc + a_koff) * 2;
        uint32_t ah0[4], al0[4], ah1[4], al1[4];
        ldm_x4(ah0, sXh + a0off);
        ldm_x4(al0, sXl + a0off);
        ldm_x4(ah1, sXh + a1off);
        ldm_x4(al1, sXl + a1off);
#pragma unroll
        for (int np = 0; np < 2; ++np) {
            const uint32_t boff = (uint32_t)((wn + np * 16 + b_row) * PSTR + kc + b_koff) * 2;
            uint32_t bh_[4], bl_[4];
            ldm_x4(bh_, sWh + boff);
            ldm_x4(bl_, sWl + boff);
            // chain P: hh + lh ; chain Q: hl  (independent accumulators)
            mma16816(accP[0][2 * np + 0], ah0, bh_ + 0);
            mma16816(accP[0][2 * np + 1], ah0, bh_ + 2);
            mma16816(accQ[0][2 * np + 0], ah0, bl_ + 0);
            mma16816(accQ[0][2 * np + 1], ah0, bl_ + 2);
            mma16816(accP[1][2 * np + 0], ah1, bh_ + 0);
            mma16816(accP[1][2 * np + 1], ah1, bh_ + 2);
            mma16816(accQ[1][2 * np + 0], ah1, bl_ + 0);
            mma16816(accQ[1][2 * np + 1], ah1, bl_ + 2);
            mma16816(accP[0][2 * np + 0], al0, bh_ + 0);
            mma16816(accP[0][2 * np + 1], al0, bh_ + 2);
            mma16816(accP[1][2 * np + 0], al1, bh_ + 0);
            mma16816(accP[1][2 * np + 1], al1, bh_ + 2);
        }
    }

    const int gid = lane >> 2;
    const int tig = lane & 3;
#pragma unroll
    for (int mt = 0; mt < 2; ++mt) {
        const int r = row0 + wm + mt * 16 + gid;
#pragma unroll
        for (int nt = 0; nt < 4; ++nt) {
            const int col = wn + nt * 8 + tig * 2;
            float b0 = sbias[col], b1 = sbias[col + 1];
            float x0 = accP[mt][nt][0] + accQ[mt][nt][0] + b0;
            float x1 = accP[mt][nt][1] + accQ[mt][nt][1] + b1;
            float y0 = accP[mt][nt][2] + accQ[mt][nt][2] + b0;
            float y1 = accP[mt][nt][3] + accQ[mt][nt][3] + b1;
            if (SPLIT_OUT) {
                *(uint32_t*)&Oh[(size_t)r * 128 + col]       = pack_hi(x0, x1);
                *(uint32_t*)&Ol[(size_t)r * 128 + col]       = pack_lo(x0, x1);
                *(uint32_t*)&Oh[(size_t)(r + 8) * 128 + col] = pack_hi(y0, y1);
                *(uint32_t*)&Ol[(size_t)(r + 8) * 128 + col] = pack_lo(y0, y1);
            } else {
                *(float2*)&C[(size_t)r * 128 + col]       = make_float2(x0, x1);
                *(float2*)&C[(size_t)(r + 8) * 128 + col] = make_float2(y0, y1);
            }
        }
    }
}

__global__ __launch_bounds__(512) void proj_qkv3(
    const float* __restrict__ X,
    const float* __restrict__ Wq, const float* __restrict__ bq,
    const float* __restrict__ Wk, const float* __restrict__ bk,
    const float* __restrict__ Wv, const float* __restrict__ bv,
    __nv_bfloat16* __restrict__ Qh, __nv_bfloat16* __restrict__ Ql,
    __nv_bfloat16* __restrict__ Kh, __nv_bfloat16* __restrict__ Kl,
    __nv_bfloat16* __restrict__ Vh, __nv_bfloat16* __restrict__ Vl)
{
    const float* Wm; const float* bias;
    __nv_bfloat16* Oh; __nv_bfloat16* Ol;
    if (blockIdx.y == 0)      { Wm = Wq; bias = bq; Oh = Qh; Ol = Ql; }
    else if (blockIdx.y == 1) { Wm = Wk; bias = bk; Oh = Kh; Ol = Kl; }
    else                      { Wm = Wv; bias = bv; Oh = Vh; Ol = Vl; }
    proj_body<true>(X, Wm, bias, nullptr, Oh, Ol);
}

__global__ __launch_bounds__(512) void proj_mma(
    const float* __restrict__ X, const float* __restrict__ Wm,
    const float* __restrict__ bias, float* __restrict__ C)
{
    proj_body<false>(X, Wm, bias, C, nullptr, nullptr);
}

// ===========================================================================
// Tensor-core sliding-window attention (R11 tiling) with 3-way split PV
// accumulators (chain 27 -> 9 serial MMAs).
// ===========================================================================
#define QSTR 24
#define VSTR 200
#define ESTR 132

#define AOFF_QH  0
#define AOFF_QL  (AOFF_QH + 64*QSTR*2)       // 3072
#define AOFF_KH  (AOFF_QL + 64*QSTR*2)       // 6144
#define AOFF_KL  (AOFF_KH + 192*QSTR*2)      // 15360
#define AOFF_VTH (AOFF_KL + 192*QSTR*2)      // 24576
#define AOFF_VTL (AOFF_VTH + 16*VSTR*2)      // 30976
#define AOFF_INV (AOFF_VTL + 16*VSTR*2)      // 37376
#define AOFF_E   (AOFF_INV + 256 + 8)        // 37640 (8B pre-guard)
#define ATTN_SMEM (AOFF_E + 64*ESTR*2)       // 54536

__global__ __launch_bounds__(128, 4) void attn_tc(
    const __nv_bfloat16* __restrict__ Qh, const __nv_bfloat16* __restrict__ Ql,
    const __nv_bfloat16* __restrict__ Kh, const __nv_bfloat16* __restrict__ Kl,
    const __nv_bfloat16* __restrict__ Vh, const __nv_bfloat16* __restrict__ Vl,
    float* __restrict__ AO, float* __restrict__ probs)
{
    extern __shared__ __align__(16) char asm_[];
    const int t = threadIdx.x;
    const int wid = t >> 5;
    const int lane = t & 31;
    const int n0 = blockIdx.x * 64;
    const int h  = blockIdx.y;
    const int b  = blockIdx.z;
    const size_t bbase = (size_t)b * Nn * En;
    const int hoff = h * Dn;

    __nv_bfloat16* sQh = (__nv_bfloat16*)(asm_ + AOFF_QH);
    __nv_bfloat16* sQl = (__nv_bfloat16*)(asm_ + AOFF_QL);
    __nv_bfloat16* sKh = (__nv_bfloat16*)(asm_ + AOFF_KH);
    __nv_bfloat16* sKl = (__nv_bfloat16*)(asm_ + AOFF_KL);
    __nv_bfloat16* sVth = (__nv_bfloat16*)(asm_ + AOFF_VTH);
    __nv_bfloat16* sVtl = (__nv_bfloat16*)(asm_ + AOFF_VTL);
    float* sInv = (float*)(asm_ + AOFF_INV);
    __half* sE  = (__half*)(asm_ + AOFF_E);

    {
        int r  = t >> 1;
        int c8 = (t & 1) * 8;
        size_t g = bbase + (size_t)(n0 + r) * En + hoff + c8;
        *(uint4*)&sQh[r * QSTR + c8] = *(const uint4*)&Qh[g];
        *(uint4*)&sQl[r * QSTR + c8] = *(const uint4*)&Ql[g];
    }
#pragma unroll
    for (int i = 0; i < 3; ++i) {
        int idx = t + i * 128;
        int r  = idx >> 1;
        int c8 = (idx & 1) * 8;
        int n = n0 - WINn + r;
        uint4 kh = make_uint4(0, 0, 0, 0), kl = kh, vh = kh, vl = kh;
        if (n >= 0 && n < Nn) {
            size_t g = bbase + (size_t)n * En + hoff + c8;
            kh = *(const uint4*)&Kh[g];
            kl = *(const uint4*)&Kl[g];
            vh = *(const uint4*)&Vh[g];
            vl = *(const uint4*)&Vl[g];
        }
        *(uint4*)&sKh[r * QSTR + c8] = kh;
        *(uint4*)&sKl[r * QSTR + c8] = kl;
        const __nv_bfloat16* vhp = (const __nv_bfloat16*)&vh;
        const __nv_bfloat16* vlp = (const __nv_bfloat16*)&vl;
#pragma unroll
        for (int j = 0; j < 8; ++j) {
            sVth[(c8 + j) * VSTR + r] = vhp[j];
            sVtl[(c8 + j) * VSTR + r] = vlp[j];
        }
    }
    __syncthreads();

    const int wq = wid * 16;
    const int gid = lane >> 2;
    const int tig = lane & 3;
    const int a_row  = (lane & 7) + ((lane >> 3) & 1) * 8;
    const int a_koff = (lane >> 4) * 8;
    const int b_row  = (lane & 7) + ((lane >> 4) & 1) * 8;
    const int b_koff = ((lane >> 3) & 1) * 8;

    const uint32_t uQh = smem_u32(sQh), uQl = smem_u32(sQl);
    const uint32_t uKh = smem_u32(sKh), uKl = smem_u32(sKl);
    const uint32_t uVh = smem_u32(sVth), uVl = smem_u32(sVtl);

    uint32_t qh[4], ql[4];
    ldm_x4(qh, uQh + (uint32_t)((wq + a_row) * QSTR + a_koff) * 2);
    ldm_x4(ql, uQl + (uint32_t)((wq + a_row) * QSTR + a_koff) * 2);

    const int r0 = wq + gid;
    const int r1 = r0 + 8;
    __half* Er0 = sE + r0 * ESTR + (r0 & 1);
    __half* Er1 = sE + r1 * ESTR + (r1 & 1);
    float sum0 = 0.f, sum1 = 0.f;
    float oA[2][4], oB[2][4], oC[2][4];
#pragma unroll
    for (int nt = 0; nt < 2; ++nt)
#pragma unroll
        for (int c = 0; c < 4; ++c) { oA[nt][c] = 0.f; oB[nt][c] = 0.f; oC[nt][c] = 0.f; }

    // Warp-local key range: keys [wq, wq+143] = 9 blocks of 16.
#pragma unroll 1
    for (int j = 0; j < 9; ++j) {
        const int kb = wq + j * 16;
        uint32_t kh[4], kl[4];
        ldm_x4(kh, uKh + (uint32_t)((kb + b_row) * QSTR + b_koff) * 2);
        ldm_x4(kl, uKl + (uint32_t)((kb + b_row) * QSTR + b_koff) * 2);

        float s0[4] = {0.f,0.f,0.f,0.f}, s1[4] = {0.f,0.f,0.f,0.f};
        mma16816(s0, qh, kh + 0); mma16816(s1, qh, kh + 2);
        mma16816(s0, ql, kh + 0); mma16816(s1, ql, kh + 2);
        mma16816(s0, qh, kl + 0); mma16816(s1, qh, kl + 2);

        const int c0 = kb + 2 * tig;
        const int c1 = c0 + 8;
        const int w00 = c0 - r0, w01 = c1 - r0;
        const int w10 = c0 - r1, w11 = c1 - r1;

        float e0 = ((unsigned)w00       <= 128u) ? __expf(s0[0] * 0.25f) : 0.f;
        float e1 = ((unsigned)(w00 + 1) <= 128u) ? __expf(s0[1] * 0.25f) : 0.f;
        float e2 = ((unsigned)w10       <= 128u) ? __expf(s0[2] * 0.25f) : 0.f;
        float e3 = ((unsigned)(w10 + 1) <= 128u) ? __expf(s0[3] * 0.25f) : 0.f;
        float e4 = ((unsigned)w01       <= 128u) ? __expf(s1[0] * 0.25f) : 0.f;
        float e5 = ((unsigned)(w01 + 1) <= 128u) ? __expf(s1[1] * 0.25f) : 0.f;
        float e6 = ((unsigned)w11       <= 128u) ? __expf(s1[2] * 0.25f) : 0.f;
        float e7 = ((unsigned)(w11 + 1) <= 128u) ? __expf(s1[3] * 0.25f) : 0.f;

        sum0 += (e0 + e1) + (e4 + e5);
        sum1 += (e2 + e3) + (e6 + e7);

        if ((unsigned)(w00 + 1) <= 129u) *(__half2*)&Er0[w00] = __floats2half2_rn(e0, e1);
        if ((unsigned)(w01 + 1) <= 129u) *(__half2*)&Er0[w01] = __floats2half2_rn(e4, e5);
        if ((unsigned)(w10 + 1) <= 129u) *(__half2*)&Er1[w10] = __floats2half2_rn(e2, e3);
        if ((unsigned)(w11 + 1) <= 129u) *(__half2*)&Er1[w11] = __floats2half2_rn(e6, e7);

        uint32_t ah[4], al[4];
        ah[0] = pack_hi(e0, e1); ah[1] = pack_hi(e2, e3);
        ah[2] = pack_hi(e4, e5); ah[3] = pack_hi(e6, e7);
        al[0] = pack_lo(e0, e1); al[1] = pack_lo(e2, e3);
        al[2] = pack_lo(e4, e5); al[3] = pack_lo(e6, e7);

        uint32_t vh[4], vl[4];
        ldm_x4(vh, uVh + (uint32_t)(b_row * VSTR + kb + b_koff) * 2);
        ldm_x4(vl, uVl + (uint32_t)(b_row * VSTR + kb + b_koff) * 2);

        // 3 independent accumulator chains
        mma16816(oA[0], ah, vh + 0); mma16816(oA[1], ah, vh + 2);
        mma16816(oB[0], al, vh + 0); mma16816(oB[1], al, vh + 2);
        mma16816(oC[0], ah, vl + 0); mma16816(oC[1], ah, vl + 2);
    }

    sum0 += __shfl_xor_sync(0xFFFFFFFFu, sum0, 1);
    sum0 += __shfl_xor_sync(0xFFFFFFFFu, sum0, 2);
    sum1 += __shfl_xor_sync(0xFFFFFFFFu, sum1, 1);
    sum1 += __shfl_xor_sync(0xFFFFFFFFu, sum1, 2);
    float inv0 = 1.0f / sum0;
    float inv1 = 1.0f / sum1;
    if (tig == 0) { sInv[r0] = inv0; sInv[r1] = inv1; }
    __syncwarp();

    {
        float o00 = oA[0][0] + oB[0][0] + oC[0][0];
        float o01 = oA[0][1] + oB[0][1] + oC[0][1];
        float o02 = oA[0][2] + oB[0][2] + oC[0][2];
        float o03 = oA[0][3] + oB[0][3] + oC[0][3];
        float o10 = oA[1][0] + oB[1][0] + oC[1][0];
        float o11 = oA[1][1] + oB[1][1] + oC[1][1];
        float o12 = oA[1][2] + oB[1][2] + oC[1][2];
        float o13 = oA[1][3] + oB[1][3] + oC[1][3];
        float* a0 = &AO[bbase + (size_t)(n0 + r0) * En + hoff];
        float* a1 = &AO[bbase + (size_t)(n0 + r1) * En + hoff];
        *(float2*)&a0[2 * tig]     = make_float2(o00 * inv0, o01 * inv0);
        *(float2*)&a1[2 * tig]     = make_float2(o02 * inv1, o03 * inv1);
        *(float2*)&a0[8 + 2 * tig] = make_float2(o10 * inv0, o11 * inv0);
        *(float2*)&a1[8 + 2 * tig] = make_float2(o12 * inv1, o13 * inv1);
    }

    if (probs) {
        const size_t pbase = ((size_t)(b * Hn + h) * Nn + n0) * Wn;
#pragma unroll 1
        for (int rl = 0; rl < 16; ++rl) {
            int r = wq + rl;
            float inv = sInv[r];
            const __half* Er = sE + r * ESTR + (r & 1);
            float* pr = probs + pbase + (size_t)r * Wn;
#pragma unroll
            for (int w0 = 0; w0 < 128; w0 += 32)
                pr[w0 + lane] = __half2float(Er[w0 + lane]) * inv;
            if (lane == 0) pr[128] = __half2float(Er[128]) * inv;
        }
    }
}

// ---------------------------------------------------------------------------
extern "C" void kernel_launch(void* const* d_in, const int* in_sizes, int n_in,
                              void* d_out, int out_size)
{
    const float* x  = (const float*)d_in[0];
    const float* Wq = (const float*)d_in[1];
    const float* bq = (const float*)d_in[2];
    const float* Wk = (const float*)d_in[3];
    const float* bk = (const float*)d_in[4];
    const float* Wv = (const float*)d_in[5];
    const float* bv = (const float*)d_in[6];
    const float* Wo = (const float*)d_in[7];
    const float* bo = (const float*)d_in[8];

    __nv_bfloat16 *pQh, *pQl, *pKh, *pKl, *pVh, *pVl;
    float *pAO, *pScr;
    cudaGetSymbolAddress((void**)&pQh, g_Qh);
    cudaGetSymbolAddress((void**)&pQl, g_Ql);
    cudaGetSymbolAddress((void**)&pKh, g_Kh);
    cudaGetSymbolAddress((void**)&pKl, g_Kl);
    cudaGetSymbolAddress((void**)&pVh, g_Vh);
    cudaGetSymbolAddress((void**)&pVl, g_Vl);
    cudaGetSymbolAddress((void**)&pAO, g_AO);
    cudaGetSymbolAddress((void**)&pScr, g_scr);

    const long OUT_ELEMS   = (long)Bn * Nn * En;
    const long PROBS_ELEMS = (long)Bn * Hn * Nn * Wn;

    float* out_ptr;
    float* probs_ptr;
    if ((long)out_size == OUT_ELEMS + PROBS_ELEMS) {
        out_ptr = (float*)d_out;
        probs_ptr = (float*)d_out + OUT_ELEMS;
    } else if ((long)out_size == PROBS_ELEMS) {
        out_ptr = pScr;
        probs_ptr = (float*)d_out;
    } else {
        out_ptr = (float*)d_out;
        probs_ptr = nullptr;
    }

    cudaFuncSetAttribute(proj_qkv3, cudaFuncAttributeMaxDynamicSharedMemorySize, PROJ_SMEM);
    cudaFuncSetAttribute(proj_mma, cudaFuncAttributeMaxDynamicSharedMemorySize, PROJ_SMEM);
    cudaFuncSetAttribute(attn_tc, cudaFuncAttributeMaxDynamicSharedMemorySize, ATTN_SMEM);

    // Q/K/V projections in ONE launch (grid.y = which matrix), 512 threads
    dim3 qgrid(Mrows / 128, 3, 1);
    proj_qkv3<<<qgrid, 512, PROJ_SMEM>>>(x, Wq, bq, Wk, bk, Wv, bv,
                                         pQh, pQl, pKh, pKl, pVh, pVl);

    // Attention (R11 tiling, split accumulators)
    dim3 agrid(Nn / 64, Hn, Bn);
    attn_tc<<<agrid, 128, ATTN_SMEM>>>(pQh, pQl, pKh, pKl, pVh, pVl, pAO, probs_ptr);

    // Output projection
    proj_mma<<<Mrows / 128, 512, PROJ_SMEM>>>(pAO, Wo, bo, out_ptr);
}

// round 17
// speedup vs baseline: 1.0216x; 1.0216x over previous
#include <cuda_runtime.h>
#include <cuda_bf16.h>
#include <cuda_fp16.h>
#include <cstddef>
#include <cstdint>

#define Bn   8
#define Nn   8192
#define En   128
#define Hn   8
#define Dn   16
#define WINn 64
#define Wn   129
#define Mrows (Bn*Nn)       // 65536

// Scratch (device globals; allocation-free per harness rules)
__device__ __nv_bfloat16 g_Qh[Mrows * En];
__device__ __nv_bfloat16 g_Ql[Mrows * En];
__device__ __nv_bfloat16 g_Kh[Mrows * En];
__device__ __nv_bfloat16 g_Kl[Mrows * En];
__device__ __nv_bfloat16 g_Vh[Mrows * En];
__device__ __nv_bfloat16 g_Vl[Mrows * En];
__device__ float g_AO[Mrows * En];
__device__ float g_scr[Mrows * En];

// ========================= helpers ============================
__device__ __forceinline__ uint32_t smem_u32(const void* p) {
    uint32_t a;
    asm("{ .reg .u64 t; cvta.to.shared.u64 t, %1; cvt.u32.u64 %0, t; }" : "=r"(a) : "l"(p));
    return a;
}
__device__ __forceinline__ uint32_t cvt_bf16x2(float lo, float hi) {
    uint32_t r;
    asm("cvt.rn.satfinite.bf16x2.f32 %0, %1, %2;" : "=r"(r) : "f"(hi), "f"(lo));
    return r;
}
__device__ __forceinline__ float trunc_hi(float x) {
    return __uint_as_float(__float_as_uint(x) & 0xFFFF0000u);
}
__device__ __forceinline__ uint32_t pack_hi(float f0, float f1) {
    return __byte_perm(__float_as_uint(f0), __float_as_uint(f1), 0x7632);
}
__device__ __forceinline__ uint32_t pack_lo(float f0, float f1) {
    return cvt_bf16x2(f0 - trunc_hi(f0), f1 - trunc_hi(f1));
}
__device__ __forceinline__ void ldm_x4(uint32_t* r, uint32_t addr) {
    asm volatile("ldmatrix.sync.aligned.m8n8.x4.shared.b16 {%0,%1,%2,%3}, [%4];"
        : "=r"(r[0]), "=r"(r[1]), "=r"(r[2]), "=r"(r[3]) : "r"(addr));
}
__device__ __forceinline__ void mma16816(float* c, const uint32_t* a, const uint32_t* b) {
    asm volatile("mma.sync.aligned.m16n8k16.row.col.f32.bf16.bf16.f32 "
        "{%0,%1,%2,%3}, {%4,%5,%6,%7}, {%8,%9}, {%0,%1,%2,%3};"
        : "+f"(c[0]), "+f"(c[1]), "+f"(c[2]), "+f"(c[3])
        : "r"(a[0]), "r"(a[1]), "r"(a[2]), "r"(a[3]), "r"(b[0]), "r"(b[1]));
}

// ===========================================================================
// Projection GEMM body, M=128 tile, 512 threads = 16 warps (4m x 4n).
// SPLIT_OUT epilogue stages h/l bf16 tiles in (dead) X smem (stride 136
// halves = 272B, 16B-aligned rows) and streams out with coalesced uint4.
// ===========================================================================
#define PSTR 136
#define SSTR 136
#define TILE128 (128 * PSTR * 2)          // 34816
#define POFF_BIAS 0
#define POFF_XH 512
#define POFF_XL (512 + TILE128)
#define POFF_WH (512 + 2*TILE128)
#define POFF_WL (512 + 3*TILE128)
#define PROJ_SMEM (512 + 4*TILE128)       // 139776

template <bool SPLIT_OUT>
__device__ __forceinline__ void proj_body(
    const float* __restrict__ X, const float* __restrict__ Wm,
    const float* __restrict__ bias,
    float* __restrict__ C, __nv_bfloat16* __restrict__ Oh, __nv_bfloat16* __restrict__ Ol)
{
    extern __shared__ __align__(16) char psm[];
    float* sbias = (float*)(psm + POFF_BIAS);
    const int t = threadIdx.x;
    const int wid = t >> 5;
    const int lane = t & 31;
    const int row0 = blockIdx.x * 128;

    if (t < 128) sbias[t] = bias[t];

#pragma unroll
    for (int i = 0; i < 8; ++i) {
        int idx = t + i * 512;
        int r  = idx >> 5;
        int kq = (idx & 31) * 4;
        uint32_t so = (uint32_t)(r * PSTR + kq) * 2;
        float4 xv = *(const float4*)&X[(size_t)(row0 + r) * 128 + kq];
        *(uint2*)(psm + POFF_XH + so) = make_uint2(pack_hi(xv.x, xv.y), pack_hi(xv.z, xv.w));
        *(uint2*)(psm + POFF_XL + so) = make_uint2(pack_lo(xv.x, xv.y), pack_lo(xv.z, xv.w));
        float4 wv = *(const float4*)&Wm[(size_t)r * 128 + kq];
        *(uint2*)(psm + POFF_WH + so) = make_uint2(pack_hi(wv.x, wv.y), pack_hi(wv.z, wv.w));
        *(uint2*)(psm + POFF_WL + so) = make_uint2(pack_lo(wv.x, wv.y), pack_lo(wv.z, wv.w));
    }
    __syncthreads();

    const int wm = (wid & 3) * 32;
    const int wn = (wid >> 2) * 32;

    float accP[2][4][4], accQ[2][4][4];
#pragma unroll
    for (int mt = 0; mt < 2; ++mt)
#pragma unroll
        for (int nt = 0; nt < 4; ++nt)
#pragma unroll
            for (int c = 0; c < 4; ++c) { accP[mt][nt][c] = 0.f; accQ[mt][nt][c] = 0.f; }

    const int a_row  = (lane & 7) + ((lane >> 3) & 1) * 8;
    const int a_koff = (lane >> 4) * 8;
    const int b_row  = (lane & 7) + ((lane >> 4) & 1) * 8;
    const int b_koff = ((lane >> 3) & 1) * 8;

    const uint32_t sXh = smem_u32(psm + POFF_XH);
    const uint32_t sXl = smem_u32(psm + POFF_XL);
    const uint32_t sWh = smem_u32(psm + POFF_WH);
    const uint32_t sWl = smem_u32(psm + POFF_WL);

#pragma unroll
    for (int kc8 = 0; kc8 < 8; ++kc8) {
        const int kc = kc8 * 16;
        const uint32_t a0off = (uint32_t)((wm + a_row) * PSTR + kc + a_koff) * 2;
        const uint32_t a1off = (uint32_t)((wm + 16 + a_row) * PSTR + kc + a_koff) * 2;
        uint32_t ah0[4], al0[4], ah1[4], al1[4];
        ldm_x4(ah0, sXh + a0off);
        ldm_x4(al0, sXl + a0off);
        ldm_x4(ah1, sXh + a1off);
        ldm_x4(al1, sXl + a1off);
#pragma unroll
        for (int np = 0; np < 2; ++np) {
            const uint32_t boff = (uint32_t)((wn + np * 16 + b_row) * PSTR + kc + b_koff) * 2;
            uint32_t bh_[4], bl_[4];
            ldm_x4(bh_, sWh + boff);
            ldm_x4(bl_, sWl + boff);
            mma16816(accP[0][2 * np + 0], ah0, bh_ + 0);
            mma16816(accP[0][2 * np + 1], ah0, bh_ + 2);
            mma16816(accQ[0][2 * np + 0], ah0, bl_ + 0);
            mma16816(accQ[0][2 * np + 1], ah0, bl_ + 2);
            mma16816(accP[1][2 * np + 0], ah1, bh_ + 0);
            mma16816(accP[1][2 * np + 1], ah1, bh_ + 2);
            mma16816(accQ[1][2 * np + 0], ah1, bl_ + 0);
            mma16816(accQ[1][2 * np + 1], ah1, bl_ + 2);
            mma16816(accP[0][2 * np + 0], al0, bh_ + 0);
            mma16816(accP[0][2 * np + 1], al0, bh_ + 2);
            mma16816(accP[1][2 * np + 0], al1, bh_ + 0);
            mma16816(accP[1][2 * np + 1], al1, bh_ + 2);
        }
    }

    const int gid = lane >> 2;
    const int tig = lane & 3;
    if (SPLIT_OUT) {
        // Stage into dead X smem (stride SSTR=136 halves, 16B-aligned rows).
        __syncthreads();
        __nv_bfloat16* stH = (__nv_bfloat16*)(psm + POFF_XH);
        __nv_bfloat16* stL = (__nv_bfloat16*)(psm + POFF_XL);
#pragma unroll
        for (int mt = 0; mt < 2; ++mt) {
            const int rr = wm + mt * 16 + gid;
#pragma unroll
            for (int nt = 0; nt < 4; ++nt) {
                const int col = wn + nt * 8 + tig * 2;
                float b0 = sbias[col], b1 = sbias[col + 1];
                float x0 = accP[mt][nt][0] + accQ[mt][nt][0] + b0;
                float x1 = accP[mt][nt][1] + accQ[mt][nt][1] + b1;
                float y0 = accP[mt][nt][2] + accQ[mt][nt][2] + b0;
                float y1 = accP[mt][nt][3] + accQ[mt][nt][3] + b1;
                *(uint32_t*)&stH[rr * SSTR + col]       = pack_hi(x0, x1);
                *(uint32_t*)&stL[rr * SSTR + col]       = pack_lo(x0, x1);
                *(uint32_t*)&stH[(rr + 8) * SSTR + col] = pack_hi(y0, y1);
                *(uint32_t*)&stL[(rr + 8) * SSTR + col] = pack_lo(y0, y1);
            }
        }
        __syncthreads();
#pragma unroll
        for (int i = 0; i < 4; ++i) {
            int idx = t + i * 512;          // 0..2047 uint4s
            int row = idx >> 4;             // 0..127
            int c8  = (idx & 15) * 8;       // halves
            *(uint4*)&Oh[(size_t)(row0 + row) * 128 + c8] = *(uint4*)&stH[row * SSTR + c8];
            *(uint4*)&Ol[(size_t)(row0 + row) * 128 + c8] = *(uint4*)&stL[row * SSTR + c8];
        }
    } else {
#pragma unroll
        for (int mt = 0; mt < 2; ++mt) {
            const int r = row0 + wm + mt * 16 + gid;
#pragma unroll
            for (int nt = 0; nt < 4; ++nt) {
                const int col = wn + nt * 8 + tig * 2;
                float b0 = sbias[col], b1 = sbias[col + 1];
                float x0 = accP[mt][nt][0] + accQ[mt][nt][0] + b0;
                float x1 = accP[mt][nt][1] + accQ[mt][nt][1] + b1;
                float y0 = accP[mt][nt][2] + accQ[mt][nt][2] + b0;
                float y1 = accP[mt][nt][3] + accQ[mt][nt][3] + b1;
                *(float2*)&C[(size_t)r * 128 + col]       = make_float2(x0, x1);
                *(float2*)&C[(size_t)(r + 8) * 128 + col] = make_float2(y0, y1);
            }
        }
    }
}

__global__ __launch_bounds__(512) void proj_qkv3(
    const float* __restrict__ X,
    const float* __restrict__ Wq, const float* __restrict__ bq,
    const float* __restrict__ Wk, const float* __restrict__ bk,
    const float* __restrict__ Wv, const float* __restrict__ bv,
    __nv_bfloat16* __restrict__ Qh, __nv_bfloat16* __restrict__ Ql,
    __nv_bfloat16* __restrict__ Kh, __nv_bfloat16* __restrict__ Kl,
    __nv_bfloat16* __restrict__ Vh, __nv_bfloat16* __restrict__ Vl)
{
    const float* Wm; const float* bias;
    __nv_bfloat16* Oh; __nv_bfloat16* Ol;
    if (blockIdx.y == 0)      { Wm = Wq; bias = bq; Oh = Qh; Ol = Ql; }
    else if (blockIdx.y == 1) { Wm = Wk; bias = bk; Oh = Kh; Ol = Kl; }
    else                      { Wm = Wv; bias = bv; Oh = Vh; Ol = Vl; }
    proj_body<true>(X, Wm, bias, nullptr, Oh, Ol);
}

__global__ __launch_bounds__(512) void proj_mma(
    const float* __restrict__ X, const float* __restrict__ Wm,
    const float* __restrict__ bias, float* __restrict__ C)
{
    proj_body<false>(X, Wm, bias, C, nullptr, nullptr);
}

// ===========================================================================
// Tensor-core sliding-window attention (R14/R11 config — best measured).
// ===========================================================================
#define QSTR 24
#define VSTR 200
#define ESTR 132

#define AOFF_QH  0
#define AOFF_QL  (AOFF_QH + 64*QSTR*2)       // 3072
#define AOFF_KH  (AOFF_QL + 64*QSTR*2)       // 6144
#define AOFF_KL  (AOFF_KH + 192*QSTR*2)      // 15360
#define AOFF_VTH (AOFF_KL + 192*QSTR*2)      // 24576
#define AOFF_VTL (AOFF_VTH + 16*VSTR*2)      // 30976
#define AOFF_INV (AOFF_VTL + 16*VSTR*2)      // 37376
#define AOFF_E   (AOFF_INV + 256 + 8)        // 37640 (8B pre-guard)
#define ATTN_SMEM (AOFF_E + 64*ESTR*2)       // 54536

__global__ __launch_bounds__(128, 4) void attn_tc(
    const __nv_bfloat16* __restrict__ Qh, const __nv_bfloat16* __restrict__ Ql,
    const __nv_bfloat16* __restrict__ Kh, const __nv_bfloat16* __restrict__ Kl,
    const __nv_bfloat16* __restrict__ Vh, const __nv_bfloat16* __restrict__ Vl,
    float* __restrict__ AO, float* __restrict__ probs)
{
    extern __shared__ __align__(16) char asm_[];
    const int t = threadIdx.x;
    const int wid = t >> 5;
    const int lane = t & 31;
    const int n0 = blockIdx.x * 64;
    const int h  = blockIdx.y;
    const int b  = blockIdx.z;
    const size_t bbase = (size_t)b * Nn * En;
    const int hoff = h * Dn;

    __nv_bfloat16* sQh = (__nv_bfloat16*)(asm_ + AOFF_QH);
    __nv_bfloat16* sQl = (__nv_bfloat16*)(asm_ + AOFF_QL);
    __nv_bfloat16* sKh = (__nv_bfloat16*)(asm_ + AOFF_KH);
    __nv_bfloat16* sKl = (__nv_bfloat16*)(asm_ + AOFF_KL);
    __nv_bfloat16* sVth = (__nv_bfloat16*)(asm_ + AOFF_VTH);
    __nv_bfloat16* sVtl = (__nv_bfloat16*)(asm_ + AOFF_VTL);
    float* sInv = (float*)(asm_ + AOFF_INV);
    __half* sE  = (__half*)(asm_ + AOFF_E);

    {
        int r  = t >> 1;
        int c8 = (t & 1) * 8;
        size_t g = bbase + (size_t)(n0 + r) * En + hoff + c8;
        *(uint4*)&sQh[r * QSTR + c8] = *(const uint4*)&Qh[g];
        *(uint4*)&sQl[r * QSTR + c8] = *(const uint4*)&Ql[g];
    }
#pragma unroll
    for (int i = 0; i < 3; ++i) {
        int idx = t + i * 128;
        int r  = idx >> 1;
        int c8 = (idx & 1) * 8;
        int n = n0 - WINn + r;
        uint4 kh = make_uint4(0, 0, 0, 0), kl = kh, vh = kh, vl = kh;
        if (n >= 0 && n < Nn) {
            size_t g = bbase + (size_t)n * En + hoff + c8;
            kh = *(const uint4*)&Kh[g];
            kl = *(const uint4*)&Kl[g];
            vh = *(const uint4*)&Vh[g];
            vl = *(const uint4*)&Vl[g];
        }
        *(uint4*)&sKh[r * QSTR + c8] = kh;
        *(uint4*)&sKl[r * QSTR + c8] = kl;
        const __nv_bfloat16* vhp = (const __nv_bfloat16*)&vh;
        const __nv_bfloat16* vlp = (const __nv_bfloat16*)&vl;
#pragma unroll
        for (int j = 0; j < 8; ++j) {
            sVth[(c8 + j) * VSTR + r] = vhp[j];
            sVtl[(c8 + j) * VSTR + r] = vlp[j];
        }
    }
    __syncthreads();

    const int wq = wid * 16;
    const int gid = lane >> 2;
    const int tig = lane & 3;
    const int a_row  = (lane & 7) + ((lane >> 3) & 1) * 8;
    const int a_koff = (lane >> 4) * 8;
    const int b_row  = (lane & 7) + ((lane >> 4) & 1) * 8;
    const int b_koff = ((lane >> 3) & 1) * 8;

    const uint32_t uQh = smem_u32(sQh), uQl = smem_u32(sQl);
    const uint32_t uKh = smem_u32(sKh), uKl = smem_u32(sKl);
    const uint32_t uVh = smem_u32(sVth), uVl = smem_u32(sVtl);

    uint32_t qh[4], ql[4];
    ldm_x4(qh, uQh + (uint32_t)((wq + a_row) * QSTR + a_koff) * 2);
    ldm_x4(ql, uQl + (uint32_t)((wq + a_row) * QSTR + a_koff) * 2);

    const int r0 = wq + gid;
    const int r1 = r0 + 8;
    __half* Er0 = sE + r0 * ESTR + (r0 & 1);
    __half* Er1 = sE + r1 * ESTR + (r1 & 1);
    float sum0 = 0.f, sum1 = 0.f;
    float oacc[2][4] = {{0.f,0.f,0.f,0.f},{0.f,0.f,0.f,0.f}};

#pragma unroll 1
    for (int j = 0; j < 9; ++j) {
        const int kb = wq + j * 16;
        uint32_t kh[4], kl[4];
        ldm_x4(kh, uKh + (uint32_t)((kb + b_row) * QSTR + b_koff) * 2);
        ldm_x4(kl, uKl + (uint32_t)((kb + b_row) * QSTR + b_koff) * 2);

        float s0[4] = {0.f,0.f,0.f,0.f}, s1[4] = {0.f,0.f,0.f,0.f};
        mma16816(s0, qh, kh + 0); mma16816(s1, qh, kh + 2);
        mma16816(s0, ql, kh + 0); mma16816(s1, ql, kh + 2);
        mma16816(s0, qh, kl + 0); mma16816(s1, qh, kl + 2);

        const int c0 = kb + 2 * tig;
        const int c1 = c0 + 8;
        const int w00 = c0 - r0, w01 = c1 - r0;
        const int w10 = c0 - r1, w11 = c1 - r1;

        float e0 = ((unsigned)w00       <= 128u) ? __expf(s0[0] * 0.25f) : 0.f;
        float e1 = ((unsigned)(w00 + 1) <= 128u) ? __expf(s0[1] * 0.25f) : 0.f;
        float e2 = ((unsigned)w10       <= 128u) ? __expf(s0[2] * 0.25f) : 0.f;
        float e3 = ((unsigned)(w10 + 1) <= 128u) ? __expf(s0[3] * 0.25f) : 0.f;
        float e4 = ((unsigned)w01       <= 128u) ? __expf(s1[0] * 0.25f) : 0.f;
        float e5 = ((unsigned)(w01 + 1) <= 128u) ? __expf(s1[1] * 0.25f) : 0.f;
        float e6 = ((unsigned)w11       <= 128u) ? __expf(s1[2] * 0.25f) : 0.f;
        float e7 = ((unsigned)(w11 + 1) <= 128u) ? __expf(s1[3] * 0.25f) : 0.f;

        sum0 += (e0 + e1) + (e4 + e5);
        sum1 += (e2 + e3) + (e6 + e7);

        if ((unsigned)(w00 + 1) <= 129u) *(__half2*)&Er0[w00] = __floats2half2_rn(e0, e1);
        if ((unsigned)(w01 + 1) <= 129u) *(__half2*)&Er0[w01] = __floats2half2_rn(e4, e5);
        if ((unsigned)(w10 + 1) <= 129u) *(__half2*)&Er1[w10] = __floats2half2_rn(e2, e3);
        if ((unsigned)(w11 + 1) <= 129u) *(__half2*)&Er1[w11] = __floats2half2_rn(e6, e7);

        uint32_t ah[4], al[4];
        ah[0] = pack_hi(e0, e1); ah[1] = pack_hi(e2, e3);
        ah[2] = pack_hi(e4, e5); ah[3] = pack_hi(e6, e7);
        al[0] = pack_lo(e0, e1); al[1] = pack_lo(e2, e3);
        al[2] = pack_lo(e4, e5); al[3] = pack_lo(e6, e7);

        uint32_t vh[4], vl[4];
        ldm_x4(vh, uVh + (uint32_t)(b_row * VSTR + kb + b_koff) * 2);
        ldm_x4(vl, uVl + (uint32_t)(b_row * VSTR + kb + b_koff) * 2);

        mma16816(oacc[0], ah, vh + 0); mma16816(oacc[1], ah, vh + 2);
        mma16816(oacc[0], al, vh + 0); mma16816(oacc[1], al, vh + 2);
        mma16816(oacc[0], ah, vl + 0); mma16816(oacc[1], ah, vl + 2);
    }

    sum0 += __shfl_xor_sync(0xFFFFFFFFu, sum0, 1);
    sum0 += __shfl_xor_sync(0xFFFFFFFFu, sum0, 2);
    sum1 += __shfl_xor_sync(0xFFFFFFFFu, sum1, 1);
    sum1 += __shfl_xor_sync(0xFFFFFFFFu, sum1, 2);
    float inv0 = 1.0f / sum0;
    float inv1 = 1.0f / sum1;
    if (tig == 0) { sInv[r0] = inv0; sInv[r1] = inv1; }
    __syncwarp();

    {
        float* a0 = &AO[bbase + (size_t)(n0 + r0) * En + hoff];
        float* a1 = &AO[bbase + (size_t)(n0 + r1) * En + hoff];
        *(float2*)&a0[2 * tig]     = make_float2(oacc[0][0] * inv0, oacc[0][1] * inv0);
        *(float2*)&a1[2 * tig]     = make_float2(oacc[0][2] * inv1, oacc[0][3] * inv1);
        *(float2*)&a0[8 + 2 * tig] = make_float2(oacc[1][0] * inv0, oacc[1][1] * inv0);
        *(float2*)&a1[8 + 2 * tig] = make_float2(oacc[1][2] * inv1, oacc[1][3] * inv1);
    }

    if (probs) {
        const size_t pbase = ((size_t)(b * Hn + h) * Nn + n0) * Wn;
#pragma unroll 1
        for (int rl = 0; rl < 16; ++rl) {
            int r = wq + rl;
            float inv = sInv[r];
            const __half* Er = sE + r * ESTR + (r & 1);
            float* pr = probs + pbase + (size_t)r * Wn;
#pragma unroll
            for (int w0 = 0; w0 < 128; w0 += 32)
                pr[w0 + lane] = __half2float(Er[w0 + lane]) * inv;
            if (lane == 0) pr[128] = __half2float(Er[128]) * inv;
        }
    }
}

// ---------------------------------------------------------------------------
extern "C" void kernel_launch(void* const* d_in, const int* in_sizes, int n_in,
                              void* d_out, int out_size)
{
    const float* x  = (const float*)d_in[0];
    const float* Wq = (const float*)d_in[1];
    const float* bq = (const float*)d_in[2];
    const float* Wk = (const float*)d_in[3];
    const float* bk = (const float*)d_in[4];
    const float* Wv = (const float*)d_in[5];
    const float* bv = (const float*)d_in[6];
    const float* Wo = (const float*)d_in[7];
    const float* bo = (const float*)d_in[8];

    __nv_bfloat16 *pQh, *pQl, *pKh, *pKl, *pVh, *pVl;
    float *pAO, *pScr;
    cudaGetSymbolAddress((void**)&pQh, g_Qh);
    cudaGetSymbolAddress((void**)&pQl, g_Ql);
    cudaGetSymbolAddress((void**)&pKh, g_Kh);
    cudaGetSymbolAddress((void**)&pKl, g_Kl);
    cudaGetSymbolAddress((void**)&pVh, g_Vh);
    cudaGetSymbolAddress((void**)&pVl, g_Vl);
    cudaGetSymbolAddress((void**)&pAO, g_AO);
    cudaGetSymbolAddress((void**)&pScr, g_scr);

    const long OUT_ELEMS   = (long)Bn * Nn * En;
    const long PROBS_ELEMS = (long)Bn * Hn * Nn * Wn;

    float* out_ptr;
    float* probs_ptr;
    if ((long)out_size == OUT_ELEMS + PROBS_ELEMS) {
        out_ptr = (float*)d_out;
        probs_ptr = (float*)d_out + OUT_ELEMS;
    } else if ((long)out_size == PROBS_ELEMS) {
        out_ptr = pScr;
        probs_ptr = (float*)d_out;
    } else {
        out_ptr = (float*)d_out;
        probs_ptr = nullptr;
    }

    cudaFuncSetAttribute(proj_qkv3, cudaFuncAttributeMaxDynamicSharedMemorySize, PROJ_SMEM);
    cudaFuncSetAttribute(proj_mma, cudaFuncAttributeMaxDynamicSharedMemorySize, PROJ_SMEM);
    cudaFuncSetAttribute(attn_tc, cudaFuncAttributeMaxDynamicSharedMemorySize, ATTN_SMEM);

    // Q/K/V projections in ONE launch (grid.y = which matrix), 512 threads
    dim3 qgrid(Mrows / 128, 3, 1);
    proj_qkv3<<<qgrid, 512, PROJ_SMEM>>>(x, Wq, bq, Wk, bk, Wv, bv,
                                         pQh, pQl, pKh, pKl, pVh, pVl);

    // Attention (R14 config)
    dim3 agrid(Nn / 64, Hn, Bn);
    attn_tc<<<agrid, 128, ATTN_SMEM>>>(pQh, pQl, pKh, pKl, pVh, pVl, pAO, probs_ptr);

    // Output projection
    proj_mma<<<Mrows / 128, 512, PROJ_SMEM>>>(pAO, Wo, bo, out_ptr);
}